// round 17
// baseline (speedup 1.0000x reference)
#include <cuda_runtime.h>
#include <math.h>

#define BQ 300   // predictions (columns of LSA)
#define BT 50    // truths (rows of LSA)
#define NB 32    // batch
#define NTHREADS 320
#define KPL 10   // columns per lane (32*10 = 320 >= 300)
#define UMAX64 0xFFFFFFFFFFFFFFFFULL
#define IDXMASK 511ULL

// Fixed-point scale 2^40: f32 costs convert exactly; solver is exact int64.
// Costs biased by +4 (uniform shift, matching-invariant) so every packed key
// is nonnegative: unsigned min == argmin with lowest-j tie-break.
#define FIXSCALE 1099511627776.0
#define CBIAS    (4LL << 40)

extern __shared__ unsigned long long cfixp[];   // BT*BQ packed ((c+B)<<9)|j

__global__ __launch_bounds__(NTHREADS, 1)
void hungarian_kernel(const float* __restrict__ pred,
                      const float* __restrict__ truth,
                      float* __restrict__ out)
{
    __shared__ float st[BT * 4];
    __shared__ unsigned long long u9[BT];     // row duals, <<9 space
    __shared__ unsigned long long ss9[BQ];    // frozen shortest, <<9 space
    __shared__ unsigned long long rmin[BT];   // packed row minima
    __shared__ unsigned long long minslot[2]; // double-buffered warp min
    __shared__ short path_s[BQ];
    __shared__ short row4col[BQ];
    __shared__ short col4row[BT];

    const int b   = blockIdx.x;
    const int tid = threadIdx.x;

    // Phase 0: stage truth boxes + init matching state
    for (int k = tid; k < BT * 4; k += NTHREADS) st[k] = truth[b * BT * 4 + k];
    for (int k = tid; k < BQ; k += NTHREADS) row4col[k] = -1;
    for (int k = tid; k < BT; k += NTHREADS) col4row[k] = -1;
    __syncthreads();

    // Phase 1: cost matrix, column-per-thread; store packed ((c+B)<<9)|j.
    if (tid < BQ) {
        const int j = tid;
        const float pcx = pred[(b * BQ + j) * 4 + 0];
        const float pcy = pred[(b * BQ + j) * 4 + 1];
        const float pw  = pred[(b * BQ + j) * 4 + 2];
        const float ph  = pred[(b * BQ + j) * 4 + 3];
        const float px0 = pcx - 0.5f * pw, py0 = pcy - 0.5f * ph;
        const float px1 = pcx + 0.5f * pw, py1 = pcy + 0.5f * ph;
        const float parea = (px1 - px0) * (py1 - py0);

        for (int i = 0; i < BT; i++) {
            const float tcx = st[i*4+0], tcy = st[i*4+1];
            const float tw  = st[i*4+2], th  = st[i*4+3];
            float l1 = fabsf(pcx - tcx) + fabsf(pcy - tcy)
                     + fabsf(pw - tw)  + fabsf(ph - th);
            float tx0 = tcx - 0.5f * tw, ty0 = tcy - 0.5f * th;
            float tx1 = tcx + 0.5f * tw, ty1 = tcy + 0.5f * th;
            float tarea = (tx1 - tx0) * (ty1 - ty0);
            float ltx = fmaxf(px0, tx0), lty = fmaxf(py0, ty0);
            float rbx = fminf(px1, tx1), rby = fminf(py1, ty1);
            float wx = fmaxf(rbx - ltx, 0.f), wy = fmaxf(rby - lty, 0.f);
            float inter = wx * wy;
            float uni   = parea + tarea - inter;
            float iou   = inter / uni;
            float ex0 = fminf(px0, tx0), ey0 = fminf(py0, ty0);
            float ex1 = fmaxf(px1, tx1), ey1 = fmaxf(py1, ty1);
            float ew = fmaxf(ex1 - ex0, 0.f), eh = fmaxf(ey1 - ey0, 0.f);
            float ae   = ew * eh;
            float giou = iou - (ae - uni) / ae;
            float c    = 5.0f * l1 - 2.0f * giou;
            const long long cf = __double2ll_rn((double)c * FIXSCALE) + CBIAS;
            cfixp[i * BQ + j] = (((unsigned long long)cf) << 9) | (unsigned)j;
        }
    }
    __syncthreads();

    // Phase 1.5: packed per-row minima (warp w handles rows w, w+10, ...)
    {
        const int w = tid >> 5, ln = tid & 31;
        for (int i = w; i < BT; i += NTHREADS / 32) {
            unsigned long long bp = UMAX64;
            #pragma unroll
            for (int k = 0; k < KPL; k++) {
                const int j = ln + 32 * k;
                if (j < BQ) {
                    const unsigned long long p = cfixp[i * BQ + j];
                    if (p < bp) bp = p;
                }
            }
            #pragma unroll
            for (int off = 16; off > 0; off >>= 1) {
                unsigned long long o = __shfl_xor_sync(0xffffffffu, bp, off);
                bp = (o < bp) ? o : bp;
            }
            if (ln == 0) rmin[i] = bp;
        }
    }
    __syncthreads();

    // Phase 2: single-warp exact JV solver.
    if (tid >= 32) return;
    const int lane = tid;

    // Greedy init: u_i = row min (feasible duals, tight matched edges).
    if (lane == 0) {
        for (int i = 0; i < BT; i++) {
            const unsigned long long p = rmin[i];
            u9[i] = p & ~IDXMASK;
            const int j = (int)(p & IDXMASK);
            if (row4col[j] < 0) { row4col[j] = (short)i; col4row[i] = (short)j; }
        }
        minslot[0] = UMAX64;
        minslot[1] = UMAX64;
    }
    __syncwarp();

    unsigned long long vv9[KPL];   // column duals v (<<9, lane-resident)
    unsigned long long sdp[KPL];   // packed shortest distances
    int                pth[KPL];   // path rows (registers, not SMEM)
    unsigned valid = 0;
    #pragma unroll
    for (int k = 0; k < KPL; k++) {
        vv9[k] = 0;
        if (lane + 32 * k < BQ) valid |= (1u << k);
    }

    for (int cur = 0; cur < BT; cur++) {
        if (col4row[cur] >= 0) continue;   // assigned by greedy init

        unsigned avail = valid, sel = 0;
        #pragma unroll
        for (int k = 0; k < KPL; k++) sdp[k] = UMAX64;
        unsigned long long lbp = UMAX64;
        if (lane == 0) { minslot[0] = UMAX64; minslot[1] = UMAX64; }
        __syncwarp();

        int i = cur, sink = -1, p = 0;
        unsigned long long mv9 = 0, ui9 = u9[cur];

        for (int guard = 0; guard <= BQ && sink < 0; guard++) {
            // Relax: pure int64 adds in pre-shifted packed space.
            const unsigned long long s9 = mv9 - ui9;
            const unsigned long long* crow = &cfixp[i * BQ];
            #pragma unroll
            for (int k = 0; k < KPL; k++) {
                if (avail & (1u << k)) {
                    const unsigned long long dp = s9 + (crow[lane + 32 * k] - vv9[k]);
                    if (dp < sdp[k]) {
                        sdp[k] = dp;
                        pth[k] = i;
                        if (dp < lbp) lbp = dp;
                    }
                }
            }
            // Warp min via one shared-memory atomic (double-buffered slot).
            atomicMin(&minslot[p], lbp);
            if (lane == 0) minslot[p ^ 1] = UMAX64;
            __syncwarp();
            const unsigned long long mp = minslot[p];
            p ^= 1;
            const int mj = (int)(mp & IDXMASK);
            mv9 = mp & ~IDXMASK;

            if (lbp == mp) {                   // winner lane (index-unique keys)
                const int kk = mj >> 5;
                sdp[kk] = UMAX64;
                avail &= ~(1u << kk);
                sel   |=  (1u << kk);
                ss9[mj]    = mv9;
                path_s[mj] = (short)pth[kk];
                lbp = UMAX64;                   // rescan lane best
                #pragma unroll
                for (int k2 = 0; k2 < KPL; k2++)
                    if (sdp[k2] < lbp) lbp = sdp[k2];
            }
            const int r = row4col[mj];
            if (r < 0) sink = mj;
            else { i = r; ui9 = u9[i]; }
        }
        __syncwarp();

        // Dual updates (pre-augmentation; exact integer algebra, <<9 space)
        #pragma unroll
        for (int k = 0; k < KPL; k++) {
            if (sel & (1u << k)) {
                const int j = lane + 32 * k;
                const unsigned long long delta = mv9 - ss9[j];
                vv9[k] -= delta;               // v[j] -= mv - shortest[j]
                const int r = row4col[j];      // pre-augment matching
                if (r >= 0) u9[r] += delta;    // distinct r per lane/k
            }
        }
        if (lane == 0) u9[cur] += mv9;
        __syncwarp();

        // Augment along the path (lane 0)
        if (lane == 0) {
            int j = sink;
            while (j >= 0) {
                const int i2 = path_s[j];
                row4col[j] = (short)i2;
                const int tmp = col4row[i2];
                col4row[i2] = (short)j;
                j = tmp;
                if (i2 == cur) break;
            }
        }
        __syncwarp();
    }

    // Output (float32): pairs sorted by pred index; rank = #(assigned preds < mine)
    for (int t = lane; t < BT; t += 32) {
        const int my = col4row[t];
        int rank = 0;
        for (int t2 = 0; t2 < BT; t2++) rank += (col4row[t2] < my) ? 1 : 0;
        out[b * 2 * BT + rank]      = (float)my;
        out[b * 2 * BT + BT + rank] = (float)t;
    }
}

extern "C" void kernel_launch(void* const* d_in, const int* in_sizes, int n_in,
                              void* d_out, int out_size)
{
    // pred_boxes (32x300x4) is the LARGER buffer in either units/order.
    const float* pred;
    const float* truth;
    if (n_in >= 2 && in_sizes[1] > in_sizes[0]) {
        pred  = (const float*)d_in[1];
        truth = (const float*)d_in[0];
    } else {
        pred  = (const float*)d_in[0];
        truth = (const float*)d_in[1];
    }
    (void)out_size;

    const int dyn_smem = BT * BQ * (int)sizeof(unsigned long long);  // 120000 B
    cudaFuncSetAttribute(hungarian_kernel,
                         cudaFuncAttributeMaxDynamicSharedMemorySize, dyn_smem);
    hungarian_kernel<<<NB, NTHREADS, dyn_smem>>>(pred, truth, (float*)d_out);
}